// round 14
// baseline (speedup 1.0000x reference)
#include <cuda_runtime.h>
#include <cuda_bf16.h>
#include <cstdint>

#define M_ROWS 65536     // B*T
#define KDIM   512       // H
#define NDIM   640       // G*V
#define GV     640
#define VPG    320
#define DPG    128
#define RPB    32
#define NBLK   (M_ROWS / RPB)

// GEMM tiling
#define MT 128
#define NT 128
#define KC 32
#define NKC (KDIM / KC)          // 16
#define APAD 8
#define LDS_STRIDE (KC + APAD)   // 40 ushorts = 80 bytes
#define TILE_U   (MT * LDS_STRIDE)          // 5120 ushorts
#define STAGE_U  (4 * TILE_U)               // 20480 ushorts
#define TILE_B   (TILE_U * 2)               // 10240 bytes
#define STAGE_B  (STAGE_U * 2)              // 40960 bytes
#define SMEM_GEMM (2 * STAGE_B)             // 81920 bytes

// fused_k: bf16 hi/lo prob planes for ldmatrix (stride 328 -> conflict-free)
#define PSTRIDE 328
#define TILE_P  (32 * PSTRIDE)              // ushorts per (group, plane)
#define SMEM_FUSED (4 * TILE_P * 2)         // 83968 bytes

// Scratch (device globals: allocation-free per harness rules)
__device__ float g_logits[(size_t)M_ROWS * NDIM];            // 160 MB
__device__ float g_partial[(size_t)NBLK * GV];               // 5.2 MB
__device__ float g_marginal[GV];
__device__ unsigned short g_wt_hi[(size_t)NDIM * KDIM];      // W^T hi [640][512]
__device__ unsigned short g_wt_lo[(size_t)NDIM * KDIM];
__device__ unsigned short g_a_hi[(size_t)M_ROWS * KDIM];     // A hi [65536][512]
__device__ unsigned short g_a_lo[(size_t)M_ROWS * KDIM];
__device__ unsigned short g_cbt_hi[2 * DPG * VPG];           // cb^T hi [g][d][v]
__device__ unsigned short g_cbt_lo[2 * DPG * VPG];

// ---------------------------------------------------------------------------
__device__ __forceinline__ void mma_bf16(float* c, const uint32_t* a, const uint32_t* b) {
    asm volatile(
        "mma.sync.aligned.m16n8k16.row.col.f32.bf16.bf16.f32 "
        "{%0,%1,%2,%3}, {%4,%5,%6,%7}, {%8,%9}, {%0,%1,%2,%3};"
        : "+f"(c[0]), "+f"(c[1]), "+f"(c[2]), "+f"(c[3])
        : "r"(a[0]), "r"(a[1]), "r"(a[2]), "r"(a[3]), "r"(b[0]), "r"(b[1]));
}
__device__ __forceinline__ void ldsm4(uint32_t* r, uint32_t addr) {
    asm volatile("ldmatrix.sync.aligned.m8n8.x4.shared.b16 {%0,%1,%2,%3}, [%4];"
        : "=r"(r[0]), "=r"(r[1]), "=r"(r[2]), "=r"(r[3]) : "r"(addr));
}
__device__ __forceinline__ unsigned short bf_hi(float x) {
    return __bfloat16_as_ushort(__float2bfloat16_rn(x));
}
__device__ __forceinline__ unsigned short bf_lo(float x, unsigned short h) {
    return __bfloat16_as_ushort(
        __float2bfloat16_rn(x - __bfloat162float(__ushort_as_bfloat16(h))));
}
__device__ __forceinline__ uint32_t smem_u32(const void* p) {
    uint32_t a;
    asm("{ .reg .u64 t; cvta.to.shared.u64 t, %1; cvt.u32.u64 %0, t; }" : "=r"(a) : "l"(p));
    return a;
}
__device__ __forceinline__ void cp_async16(uint32_t dst, const void* src) {
    asm volatile("cp.async.cg.shared.global [%0], [%1], 16;" :: "r"(dst), "l"(src));
}
#define CP_COMMIT() asm volatile("cp.async.commit_group;" ::: "memory")
#define CP_WAIT(n)  asm volatile("cp.async.wait_group %0;" :: "n"(n) : "memory")

// ---------------------------------------------------------------------------
__global__ void conv_w(const float* __restrict__ W) {
    int idx = blockIdx.x * 256 + threadIdx.x;
    if (idx >= NDIM * KDIM) return;
    int n = idx >> 9, k = idx & 511;
    float x = W[(size_t)k * NDIM + n];
    unsigned short h = bf_hi(x);
    g_wt_hi[idx] = h;
    g_wt_lo[idx] = bf_lo(x, h);
}

__global__ void conv_a(const float* __restrict__ A) {
    size_t i = (size_t)blockIdx.x * 256 + threadIdx.x;
    float4 v = ((const float4*)A)[i];
    ushort4 h, l;
    h.x = bf_hi(v.x); l.x = bf_lo(v.x, h.x);
    h.y = bf_hi(v.y); l.y = bf_lo(v.y, h.y);
    h.z = bf_hi(v.z); l.z = bf_lo(v.z, h.z);
    h.w = bf_hi(v.w); l.w = bf_lo(v.w, h.w);
    ((ushort4*)g_a_hi)[i] = h;
    ((ushort4*)g_a_lo)[i] = l;
}

// cb[1][640][128] fp32 -> cb^T hi/lo bf16 [g][d][v]
__global__ void conv_cb(const float* __restrict__ cb) {
    int idx = blockIdx.x * 256 + threadIdx.x;     // 81920
    if (idx >= 2 * VPG * DPG) return;
    int gv = idx >> 7, d = idx & 127;
    int g = gv / VPG, v = gv - g * VPG;
    float x = cb[idx];
    unsigned short h = bf_hi(x);
    int o = (g * DPG + d) * VPG + v;
    g_cbt_hi[o] = h;
    g_cbt_lo[o] = bf_lo(x, h);
}

// ---------------------------------------------------------------------------
// mma_gemm: cp.async double-buffered bf16-split mma.sync GEMM, ldmatrix frags.
// ---------------------------------------------------------------------------
__device__ __forceinline__ void issue_loads(uint32_t sbase, int m0, int n0, int kc, int tid) {
    #pragma unroll
    for (int u = 0; u < 2; ++u) {
        const int idx = u * 256 + tid;                 // 0..511
        const int r = idx >> 2, cc = idx & 3;
        const size_t ga = (size_t)(m0 + r) * KDIM + kc * KC + cc * 8;
        const size_t gb = (size_t)(n0 + r) * KDIM + kc * KC + cc * 8;
        const uint32_t so = (uint32_t)(r * LDS_STRIDE + cc * 8) * 2;  // bytes
        cp_async16(sbase + so,              g_a_hi  + ga);
        cp_async16(sbase + TILE_B + so,     g_a_lo  + ga);
        cp_async16(sbase + 2 * TILE_B + so, g_wt_hi + gb);
        cp_async16(sbase + 3 * TILE_B + so, g_wt_lo + gb);
    }
}

__global__ void __launch_bounds__(256, 2)
mma_gemm(const float* __restrict__ bias) {
    extern __shared__ unsigned short smg[];
    const uint32_t sb = smem_u32(smg);

    const int tid  = threadIdx.x;
    const int wid  = tid >> 5;
    const int lane = tid & 31;
    const int g    = lane >> 2;
    const int t    = lane & 3;
    const int n0   = blockIdx.x * NT;
    const int m0   = blockIdx.y * MT;
    const int wm   = (wid & 3) * 32;
    const int wn   = (wid >> 2) * 64;

    const uint32_t a_off = (uint32_t)((wm + (lane & 15)) * LDS_STRIDE + ((lane >> 4) << 3));
    const uint32_t b_off = (uint32_t)((wn + ((lane >> 4) << 3) + (lane & 7)) * LDS_STRIDE
                                      + (((lane >> 3) & 1) << 3));

    float c[2][8][4];
    #pragma unroll
    for (int i = 0; i < 2; i++)
        #pragma unroll
        for (int j = 0; j < 8; j++)
            #pragma unroll
            for (int q = 0; q < 4; q++) c[i][j][q] = 0.f;

    issue_loads(sb, m0, n0, 0, tid);
    CP_COMMIT();

    for (int kc = 0; kc < NKC; ++kc) {
        if (kc + 1 < NKC) {
            issue_loads(sb + ((kc + 1) & 1) * STAGE_B, m0, n0, kc + 1, tid);
            CP_COMMIT();
            CP_WAIT(1);
        } else {
            CP_WAIT(0);
        }
        __syncthreads();

        const uint32_t stage = sb + (kc & 1) * STAGE_B;
        const uint32_t aHi = stage + a_off * 2;
        const uint32_t aLo = aHi + TILE_B;
        const uint32_t bHi = stage + 2 * TILE_B + b_off * 2;
        const uint32_t bLo = bHi + TILE_B;

        #pragma unroll
        for (int ks = 0; ks < 2; ++ks) {
            const uint32_t kbb = ks * 32;          // 16 ushorts = 32 bytes
            uint32_t ah[2][4], al[2][4];
            #pragma unroll
            for (int i = 0; i < 2; ++i) {
                ldsm4(ah[i], aHi + i * (16 * LDS_STRIDE * 2) + kbb);
                ldsm4(al[i], aLo + i * (16 * LDS_STRIDE * 2) + kbb);
            }
            #pragma unroll
            for (int jp = 0; jp < 4; ++jp) {
                uint32_t bh[4], bl[4];
                ldsm4(bh, bHi + jp * (16 * LDS_STRIDE * 2) + kbb);
                ldsm4(bl, bLo + jp * (16 * LDS_STRIDE * 2) + kbb);
                #pragma unroll
                for (int jj = 0; jj < 2; ++jj) {
                    #pragma unroll
                    for (int i = 0; i < 2; ++i) {
                        mma_bf16(c[i][2 * jp + jj], ah[i], bh + 2 * jj);
                        mma_bf16(c[i][2 * jp + jj], al[i], bh + 2 * jj);
                        mma_bf16(c[i][2 * jp + jj], ah[i], bl + 2 * jj);
                    }
                }
            }
        }
        __syncthreads();
    }

    #pragma unroll
    for (int j = 0; j < 8; ++j) {
        const int col = n0 + wn + j * 8 + 2 * t;
        const float2 bv = *(const float2*)&bias[col];
        #pragma unroll
        for (int i = 0; i < 2; ++i) {
            const int row = m0 + wm + i * 16 + g;
            float2 v0 = { c[i][j][0] + bv.x, c[i][j][1] + bv.y };
            float2 v1 = { c[i][j][2] + bv.x, c[i][j][3] + bv.y };
            *(float2*)&g_logits[(size_t)row * NDIM + col]       = v0;
            *(float2*)&g_logits[(size_t)(row + 8) * NDIM + col] = v1;
        }
    }
}

// ---------------------------------------------------------------------------
// fused_k: gumbel-softmax -> bf16 hi/lo prob planes in smem, in-register
// soft-marginal, then P2 einsum on TENSOR cores (mma.sync, split bf16).
// ---------------------------------------------------------------------------
__global__ void fused_k(const float* __restrict__ gumbels,
                        const int* __restrict__ mask,
                        float* __restrict__ out) {
    extern __shared__ unsigned short probs_bf[];   // [g][plane][32][PSTRIDE]
    __shared__ float wpart[8][VPG];
    __shared__ float sm_mask[RPB];

    const int tid  = threadIdx.x;
    const int lane = tid & 31;
    const int warp = tid >> 5;
    const int r0   = blockIdx.x * RPB;

    if (tid < RPB) sm_mask[tid] = mask[r0 + tid] ? 1.0f : 0.0f;
    __syncthreads();

    // ---- P1: softmaxes; warp owns group g1 = warp&1, rows rbase+4k ----
    const int g1    = warp & 1;
    const int rbase = warp >> 1;
    const int goff  = g1 * VPG;
    unsigned short* ph = probs_bf + (g1 * 2 + 0) * TILE_P;
    unsigned short* pl = probs_bf + (g1 * 2 + 1) * TILE_P;

    float macc[10];
    #pragma unroll
    for (int j = 0; j < 10; j++) macc[j] = 0.f;

    #pragma unroll 1
    for (int k = 0; k < 8; ++k) {
        const int r = rbase + 4 * k;
        const float* lrow = &g_logits[(size_t)(r0 + r) * NDIM + goff];
        const float* grow = &gumbels [(size_t)(r0 + r) * NDIM + goff];
        float l[10], x1[10];
        float m1 = -1e30f, m2 = -1e30f;
        #pragma unroll
        for (int j = 0; j < 10; j++) {
            const int v = lane + j * 32;
            l[j]  = lrow[v];
            x1[j] = (l[j] + grow[v]) * 0.5f;
            m1 = fmaxf(m1, x1[j]); m2 = fmaxf(m2, l[j]);
        }
        #pragma unroll
        for (int o = 16; o; o >>= 1) {
            m1 = fmaxf(m1, __shfl_xor_sync(0xffffffffu, m1, o));
            m2 = fmaxf(m2, __shfl_xor_sync(0xffffffffu, m2, o));
        }
        float e1[10], e2[10], s1 = 0.f, s2 = 0.f;
        #pragma unroll
        for (int j = 0; j < 10; j++) {
            e1[j] = __expf(x1[j] - m1); s1 += e1[j];
            e2[j] = __expf(l[j]  - m2); s2 += e2[j];
        }
        #pragma unroll
        for (int o = 16; o; o >>= 1) {
            s1 += __shfl_xor_sync(0xffffffffu, s1, o);
            s2 += __shfl_xor_sync(0xffffffffu, s2, o);
        }
        const float inv1 = 1.0f / s1;
        const float inv2 = 1.0f / s2;
        const float mk = sm_mask[r];
        #pragma unroll
        for (int j = 0; j < 10; j++) {
            const int v = lane + j * 32;
            const float p = e1[j] * inv1;
            const unsigned short h = bf_hi(p);
            ph[r * PSTRIDE + v] = h;
            pl[r * PSTRIDE + v] = bf_lo(p, h);
            macc[j] = fmaf(mk, e2[j] * inv2, macc[j]);
        }
    }
    #pragma unroll
    for (int j = 0; j < 10; j++) wpart[warp][lane + j * 32] = macc[j];
    __syncthreads();

    // ---- per-block marginal partial (fixed order across 4 warps/group) ----
    for (int c = tid; c < GV; c += 256) {
        const int gg = (c >= VPG);
        const int cc = c - gg * VPG;
        g_partial[(size_t)blockIdx.x * GV + c] =
            wpart[gg][cc] + wpart[gg + 2][cc] + wpart[gg + 4][cc] + wpart[gg + 6][cc];
    }

    // ---- P2: cv = probs @ cb^T on tensor cores; warp = (g, n-quarter) ----
    const int g  = warp >> 2;
    const int nq = warp & 3;
    const uint32_t sbp = smem_u32(probs_bf);
    const uint32_t aHi = sbp + ((g * 2) * TILE_P
                         + (lane & 15) * PSTRIDE + ((lane >> 4) << 3)) * 2;
    const uint32_t aLo = aHi + TILE_P * 2;
    const unsigned short* __restrict__ cbh =
        g_cbt_hi + (size_t)g * DPG * VPG + (lane >> 2) * VPG + (lane & 3) * 2;
    const unsigned short* __restrict__ cbl =
        g_cbt_lo + (size_t)g * DPG * VPG + (lane >> 2) * VPG + (lane & 3) * 2;

    float c[2][4][4];
    #pragma unroll
    for (int i = 0; i < 2; i++)
        #pragma unroll
        for (int j = 0; j < 4; j++)
            #pragma unroll
            for (int q = 0; q < 4; q++) c[i][j][q] = 0.f;

    #pragma unroll 4
    for (int kk = 0; kk < VPG / 16; ++kk) {
        uint32_t ah[2][4], al[2][4];
        #pragma unroll
        for (int i = 0; i < 2; ++i) {
            ldsm4(ah[i], aHi + (i * 16 * PSTRIDE + kk * 16) * 2);
            ldsm4(al[i], aLo + (i * 16 * PSTRIDE + kk * 16) * 2);
        }
        #pragma unroll
        for (int jj = 0; jj < 4; ++jj) {
            const int nb = (nq * 32 + jj * 8) * VPG + kk * 16;
            uint32_t bh[2], bl[2];
            bh[0] = *(const uint32_t*)(cbh + nb);
            bh[1] = *(const uint32_t*)(cbh + nb + 8);
            bl[0] = *(const uint32_t*)(cbl + nb);
            bl[1] = *(const uint32_t*)(cbl + nb + 8);
            #pragma unroll
            for (int i = 0; i < 2; ++i) {
                mma_bf16(c[i][jj], ah[i], bh);
                mma_bf16(c[i][jj], al[i], bh);
                mma_bf16(c[i][jj], ah[i], bl);
            }
        }
    }

    #pragma unroll
    for (int jj = 0; jj < 4; ++jj) {
        const int d = nq * 32 + jj * 8 + (lane & 3) * 2;
        #pragma unroll
        for (int i = 0; i < 2; ++i) {
            const int row = r0 + i * 16 + (lane >> 2);
            *(float2*)&out[(size_t)row * 256 + g * 128 + d] =
                make_float2(c[i][jj][0], c[i][jj][1]);
            *(float2*)&out[(size_t)(row + 8) * 256 + g * 128 + d] =
                make_float2(c[i][jj][2], c[i][jj][3]);
        }
    }
}

// ---------------------------------------------------------------------------
__global__ void reduce_marginal_k() {
    const int lane = threadIdx.x & 31;
    const int warp = threadIdx.x >> 5;
    const int c = blockIdx.x * 32 + lane;
    float s = 0.f;
    for (int b = warp; b < NBLK; b += 8)
        s += g_partial[(size_t)b * GV + c];
    __shared__ float red[8][32];
    red[warp][lane] = s;
    __syncthreads();
    if (warp == 0) {
        float v = red[0][lane];
        #pragma unroll
        for (int i = 1; i < 8; i++) v += red[i][lane];
        g_marginal[c] = v;
    }
}

// ---------------------------------------------------------------------------
__global__ void finalize_k(const int* __restrict__ mask,
                           float* __restrict__ out, int out_size) {
    __shared__ double red0[1024], red1[1024];
    __shared__ int    redi[1024];
    const int tid = threadIdx.x;
    const int4* m4 = (const int4*)mask;
    int cnt = 0;
    for (int i = tid; i < M_ROWS / 4; i += 1024) {
        int4 v = m4[i];
        cnt += (v.x != 0) + (v.y != 0) + (v.z != 0) + (v.w != 0);
    }
    redi[tid] = cnt; __syncthreads();
    for (int o = 512; o; o >>= 1) { if (tid < o) redi[tid] += redi[tid + o]; __syncthreads(); }
    const double inv = 1.0 / (double)redi[0];

    double s0 = 0.0, s1 = 0.0;
    for (int c = tid; c < GV; c += 1024) {
        const double m = (double)g_marginal[c] * inv;
        const double tt = m * log(m + 1e-7);
        if (c < VPG) s0 += tt; else s1 += tt;
    }
    red0[tid] = s0; red1[tid] = s1; __syncthreads();
    for (int o = 512; o; o >>= 1) {
        if (tid < o) { red0[tid] += red0[tid + o]; red1[tid] += red1[tid + o]; }
        __syncthreads();
    }
    if (tid == 0) out[out_size - 1] = (float)(exp(-red0[0]) + exp(-red1[0]));
}

// ---------------------------------------------------------------------------
extern "C" void kernel_launch(void* const* d_in, const int* in_sizes, int n_in,
                              void* d_out, int out_size) {
    const float* hs   = (const float*)d_in[0];
    const float* gum  = (const float*)d_in[1];
    const float* W    = (const float*)d_in[2];
    const float* bias = (const float*)d_in[3];
    const float* cb   = (const float*)d_in[4];
    const int*   mask = (const int*)d_in[5];
    float* out = (float*)d_out;

    static int attr_done = 0;
    if (!attr_done) {
        cudaFuncSetAttribute(mma_gemm, cudaFuncAttributeMaxDynamicSharedMemorySize, SMEM_GEMM);
        cudaFuncSetAttribute(fused_k,  cudaFuncAttributeMaxDynamicSharedMemorySize, SMEM_FUSED);
        attr_done = 1;
    }

    conv_w<<<(NDIM * KDIM + 255) / 256, 256>>>(W);
    conv_cb<<<(2 * VPG * DPG + 255) / 256, 256>>>(cb);
    conv_a<<<(M_ROWS * KDIM / 4) / 256, 256>>>(hs);
    mma_gemm<<<dim3(NDIM / NT, M_ROWS / MT), 256, SMEM_GEMM>>>(bias);
    fused_k<<<NBLK, 256, SMEM_FUSED>>>(gum, mask, out);
    reduce_marginal_k<<<GV / 32, 256>>>();
    finalize_k<<<1, 1024>>>(mask, out, out_size);
}

// round 15
// speedup vs baseline: 1.7233x; 1.7233x over previous
#include <cuda_runtime.h>
#include <cuda_bf16.h>
#include <cstdint>

#define M_ROWS 65536     // B*T
#define KDIM   512       // H
#define NDIM   640       // G*V
#define GV     640
#define VPG    320
#define DPG    128
#define RPB    32
#define NBLK   (M_ROWS / RPB)

// GEMM tiling
#define MT 128
#define NT 128
#define KC 32
#define NKC (KDIM / KC)          // 16
#define LDS_STRIDE 40            // ushorts, bf16 tiles (pad 8)
#define AF_STRIDE 36             // floats, A fp32 stage (pad 4)

// gemm smem byte offsets (dynamic)
#define BPL_BYTES 10240                          // one bf16 plane tile 128x40
#define B_OFF(st, pl) (((st) * 2 + (pl)) * BPL_BYTES)        // 0..40960
#define APL_OFF(pl)   (40960 + (pl) * BPL_BYTES)             // A hi/lo planes
#define AF_BYTES      (MT * AF_STRIDE * 4)                   // 18432
#define AF_OFF(st)    (61440 + (st) * AF_BYTES)
#define SMEM_GEMM     (61440 + 2 * AF_BYTES)                 // 98304

// fused_k: bf16 hi/lo prob planes for ldmatrix (stride 328 -> conflict-free)
#define PSTRIDE 328
#define TILE_P  (32 * PSTRIDE)              // ushorts per (group, plane)
#define SMEM_FUSED (4 * TILE_P * 2)         // 83968 bytes

// Scratch (device globals: allocation-free per harness rules)
__device__ float g_logits[(size_t)M_ROWS * NDIM];            // 160 MB
__device__ float g_partial[(size_t)NBLK * GV];               // 5.2 MB
__device__ float g_marginal[GV];
__device__ unsigned short g_wt_hi[(size_t)NDIM * KDIM];      // W^T hi [640][512]
__device__ unsigned short g_wt_lo[(size_t)NDIM * KDIM];
__device__ uint4 g_cbf[2 * 16 * 20 * 32];                    // cb frag table, 320 KB

// ---------------------------------------------------------------------------
__device__ __forceinline__ void mma_bf16(float* c, const uint32_t* a, const uint32_t* b) {
    asm volatile(
        "mma.sync.aligned.m16n8k16.row.col.f32.bf16.bf16.f32 "
        "{%0,%1,%2,%3}, {%4,%5,%6,%7}, {%8,%9}, {%0,%1,%2,%3};"
        : "+f"(c[0]), "+f"(c[1]), "+f"(c[2]), "+f"(c[3])
        : "r"(a[0]), "r"(a[1]), "r"(a[2]), "r"(a[3]), "r"(b[0]), "r"(b[1]));
}
__device__ __forceinline__ void ldsm4(uint32_t* r, uint32_t addr) {
    asm volatile("ldmatrix.sync.aligned.m8n8.x4.shared.b16 {%0,%1,%2,%3}, [%4];"
        : "=r"(r[0]), "=r"(r[1]), "=r"(r[2]), "=r"(r[3]) : "r"(addr));
}
__device__ __forceinline__ unsigned short bf_hi(float x) {
    return __bfloat16_as_ushort(__float2bfloat16_rn(x));
}
__device__ __forceinline__ unsigned short bf_lo(float x, unsigned short h) {
    return __bfloat16_as_ushort(
        __float2bfloat16_rn(x - __bfloat162float(__ushort_as_bfloat16(h))));
}
__device__ __forceinline__ uint32_t smem_u32(const void* p) {
    uint32_t a;
    asm("{ .reg .u64 t; cvta.to.shared.u64 t, %1; cvt.u32.u64 %0, t; }" : "=r"(a) : "l"(p));
    return a;
}
__device__ __forceinline__ void cp_async16(uint32_t dst, const void* src) {
    asm volatile("cp.async.cg.shared.global [%0], [%1], 16;" :: "r"(dst), "l"(src));
}
#define CP_COMMIT() asm volatile("cp.async.commit_group;" ::: "memory")
#define CP_WAIT(n)  asm volatile("cp.async.wait_group %0;" :: "n"(n) : "memory")

// ---------------------------------------------------------------------------
__global__ void conv_w(const float* __restrict__ W) {
    int idx = blockIdx.x * 256 + threadIdx.x;
    if (idx >= NDIM * KDIM) return;
    int n = idx >> 9, k = idx & 511;
    float x = W[(size_t)k * NDIM + n];
    unsigned short h = bf_hi(x);
    g_wt_hi[idx] = h;
    g_wt_lo[idx] = bf_lo(x, h);
}

// cb[1][640][128] fp32 -> mma B-fragment table [g][db][kk][lane] uint4
__global__ void conv_cb(const float* __restrict__ cb) {
    int idx = blockIdx.x * 256 + threadIdx.x;     // 2*16*20*32 = 20480
    if (idx >= 2 * 16 * 20 * 32) return;
    int lane = idx & 31;
    int kk = (idx >> 5) % 20;
    int db = (idx >> 5) / 20 % 16;
    int g  = idx / (32 * 20 * 16);
    int d = db * 8 + (lane >> 2);
    int v = kk * 16 + (lane & 3) * 2;
    float x00 = cb[(size_t)(g * VPG + v)     * DPG + d];
    float x01 = cb[(size_t)(g * VPG + v + 1) * DPG + d];
    float x10 = cb[(size_t)(g * VPG + v + 8) * DPG + d];
    float x11 = cb[(size_t)(g * VPG + v + 9) * DPG + d];
    unsigned short h00 = bf_hi(x00), h01 = bf_hi(x01), h10 = bf_hi(x10), h11 = bf_hi(x11);
    uint4 f;
    f.x = (uint32_t)h00 | ((uint32_t)h01 << 16);
    f.y = (uint32_t)h10 | ((uint32_t)h11 << 16);
    f.z = (uint32_t)bf_lo(x00, h00) | ((uint32_t)bf_lo(x01, h01) << 16);
    f.w = (uint32_t)bf_lo(x10, h10) | ((uint32_t)bf_lo(x11, h11) << 16);
    g_cbf[idx] = f;
}

// ---------------------------------------------------------------------------
// mma_gemm: cp.async double-buffered bf16-split mma.sync GEMM.
// A loaded as fp32 and split to bf16 hi/lo in-kernel (conv_a folded in).
// ---------------------------------------------------------------------------
__device__ __forceinline__ void issue_loads(uint32_t sb, int stage, int m0, int n0,
                                            int kc, int tid, const float* __restrict__ A) {
    // B planes: per plane 128 rows x 64B
    #pragma unroll
    for (int u = 0; u < 2; ++u) {
        const int idx = u * 256 + tid;                 // 0..511
        const int r = idx >> 2, cc = idx & 3;
        const size_t gb = (size_t)(n0 + r) * KDIM + kc * KC + cc * 8;
        const uint32_t so = (uint32_t)(r * LDS_STRIDE + cc * 8) * 2;
        cp_async16(sb + B_OFF(stage, 0) + so, g_wt_hi + gb);
        cp_async16(sb + B_OFF(stage, 1) + so, g_wt_lo + gb);
    }
    // A fp32: 128 rows x 128B
    #pragma unroll
    for (int u = 0; u < 4; ++u) {
        const int idx = u * 256 + tid;                 // 0..1023
        const int r = idx >> 3, cc = idx & 7;
        cp_async16(sb + AF_OFF(stage) + (uint32_t)(r * AF_STRIDE + cc * 4) * 4,
                   A + (size_t)(m0 + r) * KDIM + kc * KC + cc * 4);
    }
}

__global__ void __launch_bounds__(256, 2)
mma_gemm(const float* __restrict__ A, const float* __restrict__ bias) {
    extern __shared__ char smg[];
    const uint32_t sb = smem_u32(smg);

    const int tid  = threadIdx.x;
    const int wid  = tid >> 5;
    const int lane = tid & 31;
    const int g    = lane >> 2;
    const int t    = lane & 3;
    const int n0   = blockIdx.x * NT;
    const int m0   = blockIdx.y * MT;
    const int wm   = (wid & 3) * 32;
    const int wn   = (wid >> 2) * 64;

    const uint32_t a_off = (uint32_t)((wm + (lane & 15)) * LDS_STRIDE + ((lane >> 4) << 3));
    const uint32_t b_off = (uint32_t)((wn + ((lane >> 4) << 3) + (lane & 7)) * LDS_STRIDE
                                      + (((lane >> 3) & 1) << 3));

    float c[2][8][4];
    #pragma unroll
    for (int i = 0; i < 2; i++)
        #pragma unroll
        for (int j = 0; j < 8; j++)
            #pragma unroll
            for (int q = 0; q < 4; q++) c[i][j][q] = 0.f;

    issue_loads(sb, 0, m0, n0, 0, tid, A);
    CP_COMMIT();

    for (int kc = 0; kc < NKC; ++kc) {
        const int stage = kc & 1;
        if (kc + 1 < NKC) {
            issue_loads(sb, stage ^ 1, m0, n0, kc + 1, tid, A);
            CP_COMMIT();
            CP_WAIT(1);
        } else {
            CP_WAIT(0);
        }
        __syncthreads();   // stage data ready; previous compute done

        // convert A fp32 -> bf16 hi/lo planes (single-buffered)
        {
            const int r = tid >> 1, h = tid & 1;
            const float* src = (const float*)(smg + AF_OFF(stage)) + r * AF_STRIDE + h * 16;
            unsigned short* dh = (unsigned short*)(smg + APL_OFF(0)) + r * LDS_STRIDE + h * 16;
            unsigned short* dl = (unsigned short*)(smg + APL_OFF(1)) + r * LDS_STRIDE + h * 16;
            #pragma unroll
            for (int q = 0; q < 4; ++q) {
                float4 v = *(const float4*)(src + q * 4);
                ushort4 hh, ll;
                hh.x = bf_hi(v.x); ll.x = bf_lo(v.x, hh.x);
                hh.y = bf_hi(v.y); ll.y = bf_lo(v.y, hh.y);
                hh.z = bf_hi(v.z); ll.z = bf_lo(v.z, hh.z);
                hh.w = bf_hi(v.w); ll.w = bf_lo(v.w, hh.w);
                *(ushort4*)(dh + q * 4) = hh;
                *(ushort4*)(dl + q * 4) = ll;
            }
        }
        __syncthreads();   // A planes ready

        const uint32_t aHi = sb + APL_OFF(0) + a_off * 2;
        const uint32_t aLo = sb + APL_OFF(1) + a_off * 2;
        const uint32_t bHi = sb + B_OFF(stage, 0) + b_off * 2;
        const uint32_t bLo = sb + B_OFF(stage, 1) + b_off * 2;

        #pragma unroll
        for (int ks = 0; ks < 2; ++ks) {
            const uint32_t kbb = ks * 32;          // 16 ushorts = 32 bytes
            uint32_t ah[2][4], al[2][4];
            #pragma unroll
            for (int i = 0; i < 2; ++i) {
                ldsm4(ah[i], aHi + i * (16 * LDS_STRIDE * 2) + kbb);
                ldsm4(al[i], aLo + i * (16 * LDS_STRIDE * 2) + kbb);
            }
            #pragma unroll
            for (int jp = 0; jp < 4; ++jp) {
                uint32_t bh[4], bl[4];
                ldsm4(bh, bHi + jp * (16 * LDS_STRIDE * 2) + kbb);
                ldsm4(bl, bLo + jp * (16 * LDS_STRIDE * 2) + kbb);
                #pragma unroll
                for (int jj = 0; jj < 2; ++jj) {
                    #pragma unroll
                    for (int i = 0; i < 2; ++i) {
                        mma_bf16(c[i][2 * jp + jj], ah[i], bh + 2 * jj);
                        mma_bf16(c[i][2 * jp + jj], al[i], bh + 2 * jj);
                        mma_bf16(c[i][2 * jp + jj], ah[i], bl + 2 * jj);
                    }
                }
            }
        }
        __syncthreads();   // compute done before next conversion/prefetch reuse
    }

    #pragma unroll
    for (int j = 0; j < 8; ++j) {
        const int col = n0 + wn + j * 8 + 2 * t;
        const float2 bv = *(const float2*)&bias[col];
        #pragma unroll
        for (int i = 0; i < 2; ++i) {
            const int row = m0 + wm + i * 16 + g;
            float2 v0 = { c[i][j][0] + bv.x, c[i][j][1] + bv.y };
            float2 v1 = { c[i][j][2] + bv.x, c[i][j][3] + bv.y };
            *(float2*)&g_logits[(size_t)row * NDIM + col]       = v0;
            *(float2*)&g_logits[(size_t)(row + 8) * NDIM + col] = v1;
        }
    }
}

// ---------------------------------------------------------------------------
// fused_k: gumbel-softmax -> bf16 hi/lo prob planes in smem, in-register
// soft-marginal, then P2 einsum on tensor cores fed by the coalesced
// cb fragment table.
// ---------------------------------------------------------------------------
__global__ void fused_k(const float* __restrict__ gumbels,
                        const int* __restrict__ mask,
                        float* __restrict__ out) {
    extern __shared__ unsigned short probs_bf[];   // [g][plane][32][PSTRIDE]
    __shared__ float wpart[8][VPG];
    __shared__ float sm_mask[RPB];

    const int tid  = threadIdx.x;
    const int lane = tid & 31;
    const int warp = tid >> 5;
    const int r0   = blockIdx.x * RPB;

    if (tid < RPB) sm_mask[tid] = mask[r0 + tid] ? 1.0f : 0.0f;
    __syncthreads();

    // ---- P1: softmaxes; warp owns group g1 = warp&1, rows rbase+4k ----
    const int g1    = warp & 1;
    const int rbase = warp >> 1;
    const int goff  = g1 * VPG;
    unsigned short* ph = probs_bf + (g1 * 2 + 0) * TILE_P;
    unsigned short* pl = probs_bf + (g1 * 2 + 1) * TILE_P;

    float macc[10];
    #pragma unroll
    for (int j = 0; j < 10; j++) macc[j] = 0.f;

    #pragma unroll 1
    for (int k = 0; k < 8; ++k) {
        const int r = rbase + 4 * k;
        const float* lrow = &g_logits[(size_t)(r0 + r) * NDIM + goff];
        const float* grow = &gumbels [(size_t)(r0 + r) * NDIM + goff];
        float l[10], x1[10];
        float m1 = -1e30f, m2 = -1e30f;
        #pragma unroll
        for (int j = 0; j < 10; j++) {
            const int v = lane + j * 32;
            l[j]  = lrow[v];
            x1[j] = (l[j] + grow[v]) * 0.5f;
            m1 = fmaxf(m1, x1[j]); m2 = fmaxf(m2, l[j]);
        }
        #pragma unroll
        for (int o = 16; o; o >>= 1) {
            m1 = fmaxf(m1, __shfl_xor_sync(0xffffffffu, m1, o));
            m2 = fmaxf(m2, __shfl_xor_sync(0xffffffffu, m2, o));
        }
        float e1[10], e2[10], s1 = 0.f, s2 = 0.f;
        #pragma unroll
        for (int j = 0; j < 10; j++) {
            e1[j] = __expf(x1[j] - m1); s1 += e1[j];
            e2[j] = __expf(l[j]  - m2); s2 += e2[j];
        }
        #pragma unroll
        for (int o = 16; o; o >>= 1) {
            s1 += __shfl_xor_sync(0xffffffffu, s1, o);
            s2 += __shfl_xor_sync(0xffffffffu, s2, o);
        }
        const float inv1 = 1.0f / s1;
        const float inv2 = 1.0f / s2;
        const float mk = sm_mask[r];
        #pragma unroll
        for (int j = 0; j < 10; j++) {
            const int v = lane + j * 32;
            const float p = e1[j] * inv1;
            const unsigned short h = bf_hi(p);
            ph[r * PSTRIDE + v] = h;
            pl[r * PSTRIDE + v] = bf_lo(p, h);
            macc[j] = fmaf(mk, e2[j] * inv2, macc[j]);
        }
    }
    #pragma unroll
    for (int j = 0; j < 10; j++) wpart[warp][lane + j * 32] = macc[j];
    __syncthreads();

    // ---- per-block marginal partial (fixed order across 4 warps/group) ----
    for (int c = tid; c < GV; c += 256) {
        const int gg = (c >= VPG);
        const int cc = c - gg * VPG;
        g_partial[(size_t)blockIdx.x * GV + c] =
            wpart[gg][cc] + wpart[gg + 2][cc] + wpart[gg + 4][cc] + wpart[gg + 6][cc];
    }

    // ---- P2: cv = probs @ cb^T on tensor cores; warp = (g, n-quarter) ----
    const int g  = warp >> 2;
    const int nq = warp & 3;
    const uint32_t sbp = smem_u32(probs_bf);
    const uint32_t aHi = sbp + ((g * 2) * TILE_P
                         + (lane & 15) * PSTRIDE + ((lane >> 4) << 3)) * 2;
    const uint32_t aLo = aHi + TILE_P * 2;
    const uint4* __restrict__ Fw = g_cbf + ((g * 16 + nq * 4) * 20) * 32 + lane;

    float c[2][4][4];
    #pragma unroll
    for (int i = 0; i < 2; i++)
        #pragma unroll
        for (int j = 0; j < 4; j++)
            #pragma unroll
            for (int q = 0; q < 4; q++) c[i][j][q] = 0.f;

    #pragma unroll 4
    for (int kk = 0; kk < VPG / 16; ++kk) {
        uint32_t ah[2][4], al[2][4];
        #pragma unroll
        for (int i = 0; i < 2; ++i) {
            ldsm4(ah[i], aHi + (i * 16 * PSTRIDE + kk * 16) * 2);
            ldsm4(al[i], aLo + (i * 16 * PSTRIDE + kk * 16) * 2);
        }
        #pragma unroll
        for (int jj = 0; jj < 4; ++jj) {
            const uint4 f = Fw[(jj * 20 + kk) * 32];     // coalesced LDG.128
            uint32_t bh[2] = { f.x, f.y };
            uint32_t bl[2] = { f.z, f.w };
            #pragma unroll
            for (int i = 0; i < 2; ++i) {
                mma_bf16(c[i][jj], ah[i], bh);
                mma_bf16(c[i][jj], al[i], bh);
                mma_bf16(c[i][jj], ah[i], bl);
            }
        }
    }

    #pragma unroll
    for (int jj = 0; jj < 4; ++jj) {
        const int d = nq * 32 + jj * 8 + (lane & 3) * 2;
        #pragma unroll
        for (int i = 0; i < 2; ++i) {
            const int row = r0 + i * 16 + (lane >> 2);
            *(float2*)&out[(size_t)row * 256 + g * 128 + d] =
                make_float2(c[i][jj][0], c[i][jj][1]);
            *(float2*)&out[(size_t)(row + 8) * 256 + g * 128 + d] =
                make_float2(c[i][jj][2], c[i][jj][3]);
        }
    }
}

// ---------------------------------------------------------------------------
__global__ void reduce_marginal_k() {
    const int lane = threadIdx.x & 31;
    const int warp = threadIdx.x >> 5;
    const int c = blockIdx.x * 32 + lane;
    float s = 0.f;
    for (int b = warp; b < NBLK; b += 8)
        s += g_partial[(size_t)b * GV + c];
    __shared__ float red[8][32];
    red[warp][lane] = s;
    __syncthreads();
    if (warp == 0) {
        float v = red[0][lane];
        #pragma unroll
        for (int i = 1; i < 8; i++) v += red[i][lane];
        g_marginal[c] = v;
    }
}

// ---------------------------------------------------------------------------
__global__ void finalize_k(const int* __restrict__ mask,
                           float* __restrict__ out, int out_size) {
    __shared__ double red0[1024], red1[1024];
    __shared__ int    redi[1024];
    const int tid = threadIdx.x;
    const int4* m4 = (const int4*)mask;
    int cnt = 0;
    for (int i = tid; i < M_ROWS / 4; i += 1024) {
        int4 v = m4[i];
        cnt += (v.x != 0) + (v.y != 0) + (v.z != 0) + (v.w != 0);
    }
    redi[tid] = cnt; __syncthreads();
    for (int o = 512; o; o >>= 1) { if (tid < o) redi[tid] += redi[tid + o]; __syncthreads(); }
    const double inv = 1.0 / (double)redi[0];

    double s0 = 0.0, s1 = 0.0;
    for (int c = tid; c < GV; c += 1024) {
        const double m = (double)g_marginal[c] * inv;
        const double tt = m * log(m + 1e-7);
        if (c < VPG) s0 += tt; else s1 += tt;
    }
    red0[tid] = s0; red1[tid] = s1; __syncthreads();
    for (int o = 512; o; o >>= 1) {
        if (tid < o) { red0[tid] += red0[tid + o]; red1[tid] += red1[tid + o]; }
        __syncthreads();
    }
    if (tid == 0) out[out_size - 1] = (float)(exp(-red0[0]) + exp(-red1[0]));
}

// ---------------------------------------------------------------------------
extern "C" void kernel_launch(void* const* d_in, const int* in_sizes, int n_in,
                              void* d_out, int out_size) {
    const float* hs   = (const float*)d_in[0];
    const float* gum  = (const float*)d_in[1];
    const float* W    = (const float*)d_in[2];
    const float* bias = (const float*)d_in[3];
    const float* cb   = (const float*)d_in[4];
    const int*   mask = (const int*)d_in[5];
    float* out = (float*)d_out;

    static int attr_done = 0;
    if (!attr_done) {
        cudaFuncSetAttribute(mma_gemm, cudaFuncAttributeMaxDynamicSharedMemorySize, SMEM_GEMM);
        cudaFuncSetAttribute(fused_k,  cudaFuncAttributeMaxDynamicSharedMemorySize, SMEM_FUSED);
        attr_done = 1;
    }

    conv_w<<<(NDIM * KDIM + 255) / 256, 256>>>(W);
    conv_cb<<<(2 * 16 * 20 * 32 + 255) / 256, 256>>>(cb);
    mma_gemm<<<dim3(NDIM / NT, M_ROWS / MT), 256, SMEM_GEMM>>>(hs, bias);
    fused_k<<<NBLK, 256, SMEM_FUSED>>>(gum, mask, out);
    reduce_marginal_k<<<GV / 32, 256>>>();
    finalize_k<<<1, 1024>>>(mask, out, out_size);
}

// round 16
// speedup vs baseline: 1.8316x; 1.0629x over previous
#include <cuda_runtime.h>
#include <cuda_bf16.h>
#include <cstdint>

#define M_ROWS 65536     // B*T
#define KDIM   512       // H
#define NDIM   640       // G*V
#define GV     640
#define VPG    320
#define DPG    128
#define RPB    32
#define NBLK   (M_ROWS / RPB)

// GEMM tiling
#define MT 128
#define NT 128
#define KC 32
#define NKC (KDIM / KC)          // 16
#define LDS_STRIDE 40            // ushorts, bf16 tiles (pad 8)

// gemm smem byte offsets (dynamic): B planes 2-stage + A planes 2-stage
#define BPL_BYTES 10240                               // one plane tile 128x40 bf16
#define B_OFF(st, pl)  (((st) * 2 + (pl)) * BPL_BYTES)          // 0..40960
#define APL_OFF(st, pl) (40960 + ((st) * 2 + (pl)) * BPL_BYTES) // 40960..81920
#define SMEM_GEMM 81920

// fused_k: bf16 hi/lo prob planes for ldmatrix (stride 328 -> conflict-free)
#define PSTRIDE 328
#define TILE_P  (32 * PSTRIDE)              // ushorts per (group, plane)
#define SMEM_FUSED (4 * TILE_P * 2)         // 83968 bytes

// Scratch (device globals: allocation-free per harness rules)
__device__ float g_logits[(size_t)M_ROWS * NDIM];            // 160 MB
__device__ float g_partial[(size_t)NBLK * GV];               // 5.2 MB
__device__ float g_marginal[GV];
__device__ unsigned short g_wt_hi[(size_t)NDIM * KDIM];      // W^T hi [640][512]
__device__ unsigned short g_wt_lo[(size_t)NDIM * KDIM];
__device__ uint4 g_cbf[2 * 16 * 20 * 32];                    // cb frag table, 320 KB

// ---------------------------------------------------------------------------
__device__ __forceinline__ void mma_bf16(float* c, const uint32_t* a, const uint32_t* b) {
    asm volatile(
        "mma.sync.aligned.m16n8k16.row.col.f32.bf16.bf16.f32 "
        "{%0,%1,%2,%3}, {%4,%5,%6,%7}, {%8,%9}, {%0,%1,%2,%3};"
        : "+f"(c[0]), "+f"(c[1]), "+f"(c[2]), "+f"(c[3])
        : "r"(a[0]), "r"(a[1]), "r"(a[2]), "r"(a[3]), "r"(b[0]), "r"(b[1]));
}
__device__ __forceinline__ void ldsm4(uint32_t* r, uint32_t addr) {
    asm volatile("ldmatrix.sync.aligned.m8n8.x4.shared.b16 {%0,%1,%2,%3}, [%4];"
        : "=r"(r[0]), "=r"(r[1]), "=r"(r[2]), "=r"(r[3]) : "r"(addr));
}
__device__ __forceinline__ unsigned short bf_hi(float x) {
    return __bfloat16_as_ushort(__float2bfloat16_rn(x));
}
__device__ __forceinline__ unsigned short bf_lo(float x, unsigned short h) {
    return __bfloat16_as_ushort(
        __float2bfloat16_rn(x - __bfloat162float(__ushort_as_bfloat16(h))));
}
__device__ __forceinline__ uint32_t smem_u32(const void* p) {
    uint32_t a;
    asm("{ .reg .u64 t; cvta.to.shared.u64 t, %1; cvt.u32.u64 %0, t; }" : "=r"(a) : "l"(p));
    return a;
}
__device__ __forceinline__ void cp_async16(uint32_t dst, const void* src) {
    asm volatile("cp.async.cg.shared.global [%0], [%1], 16;" :: "r"(dst), "l"(src));
}
#define CP_COMMIT() asm volatile("cp.async.commit_group;" ::: "memory")
#define CP_WAIT(n)  asm volatile("cp.async.wait_group %0;" :: "n"(n) : "memory")

// ---------------------------------------------------------------------------
__global__ void conv_w(const float* __restrict__ W) {
    int idx = blockIdx.x * 256 + threadIdx.x;
    if (idx >= NDIM * KDIM) return;
    int n = idx >> 9, k = idx & 511;
    float x = W[(size_t)k * NDIM + n];
    unsigned short h = bf_hi(x);
    g_wt_hi[idx] = h;
    g_wt_lo[idx] = bf_lo(x, h);
}

// cb[1][640][128] fp32 -> mma B-fragment table [g][db][kk][lane] uint4
__global__ void conv_cb(const float* __restrict__ cb) {
    int idx = blockIdx.x * 256 + threadIdx.x;     // 2*16*20*32 = 20480
    if (idx >= 2 * 16 * 20 * 32) return;
    int lane = idx & 31;
    int kk = (idx >> 5) % 20;
    int db = (idx >> 5) / 20 % 16;
    int g  = idx / (32 * 20 * 16);
    int d = db * 8 + (lane >> 2);
    int v = kk * 16 + (lane & 3) * 2;
    float x00 = cb[(size_t)(g * VPG + v)     * DPG + d];
    float x01 = cb[(size_t)(g * VPG + v + 1) * DPG + d];
    float x10 = cb[(size_t)(g * VPG + v + 8) * DPG + d];
    float x11 = cb[(size_t)(g * VPG + v + 9) * DPG + d];
    unsigned short h00 = bf_hi(x00), h01 = bf_hi(x01), h10 = bf_hi(x10), h11 = bf_hi(x11);
    uint4 f;
    f.x = (uint32_t)h00 | ((uint32_t)h01 << 16);
    f.y = (uint32_t)h10 | ((uint32_t)h11 << 16);
    f.z = (uint32_t)bf_lo(x00, h00) | ((uint32_t)bf_lo(x01, h01) << 16);
    f.w = (uint32_t)bf_lo(x10, h10) | ((uint32_t)bf_lo(x11, h11) << 16);
    g_cbf[idx] = f;
}

// ---------------------------------------------------------------------------
// mma_gemm: cp.async B (double-buffered) + register-converted A planes
// (double-buffered), 2 syncs/iter, bf16-split 3-pass mma.sync.
// ---------------------------------------------------------------------------
__device__ __forceinline__ void issueB(uint32_t sb, int stage, int n0, int kc, int tid) {
    #pragma unroll
    for (int u = 0; u < 2; ++u) {
        const int idx = u * 256 + tid;                 // 0..511
        const int r = idx >> 2, cc = idx & 3;
        const size_t gb = (size_t)(n0 + r) * KDIM + kc * KC + cc * 8;
        const uint32_t so = (uint32_t)(r * LDS_STRIDE + cc * 8) * 2;
        cp_async16(sb + B_OFF(stage, 0) + so, g_wt_hi + gb);
        cp_async16(sb + B_OFF(stage, 1) + so, g_wt_lo + gb);
    }
}

__device__ __forceinline__ void ldgA(float4* a, const float* __restrict__ A,
                                     int m0, int kc, int tid) {
    const int c = (tid & 7) * 4;
    #pragma unroll
    for (int u = 0; u < 4; ++u) {
        const int r = u * 32 + (tid >> 3);
        a[u] = *(const float4*)&A[(size_t)(m0 + r) * KDIM + kc * KC + c];
    }
}

__global__ void __launch_bounds__(256, 2)
mma_gemm(const float* __restrict__ A, const float* __restrict__ bias) {
    extern __shared__ char smg[];
    const uint32_t sb = smem_u32(smg);

    const int tid  = threadIdx.x;
    const int wid  = tid >> 5;
    const int lane = tid & 31;
    const int g    = lane >> 2;
    const int t    = lane & 3;
    const int n0   = blockIdx.x * NT;
    const int m0   = blockIdx.y * MT;
    const int wm   = (wid & 3) * 32;
    const int wn   = (wid >> 2) * 64;

    const uint32_t a_off = (uint32_t)((wm + (lane & 15)) * LDS_STRIDE + ((lane >> 4) << 3));
    const uint32_t b_off = (uint32_t)((wn + ((lane >> 4) << 3) + (lane & 7)) * LDS_STRIDE
                                      + (((lane >> 3) & 1) << 3));

    float c[2][8][4];
    #pragma unroll
    for (int i = 0; i < 2; i++)
        #pragma unroll
        for (int j = 0; j < 8; j++)
            #pragma unroll
            for (int q = 0; q < 4; q++) c[i][j][q] = 0.f;

    float4 aCur[4], aNext[4];
    ldgA(aCur, A, m0, 0, tid);
    issueB(sb, 0, n0, 0, tid);
    CP_COMMIT();

    #pragma unroll 2
    for (int kc = 0; kc < NKC; ++kc) {
        const int st = kc & 1;
        __syncthreads();                          // mma(kc-1) fully done
        if (kc + 1 < NKC) { issueB(sb, st ^ 1, n0, kc + 1, tid); CP_COMMIT(); }

        // convert aCur -> bf16 hi/lo planes (stage st); planes(st) free since
        // mma(kc-2) completed before the previous sync.
        {
            const int co = (tid & 7) * 4;
            unsigned short* dh = (unsigned short*)(smg + APL_OFF(st, 0)) + co;
            unsigned short* dl = (unsigned short*)(smg + APL_OFF(st, 1)) + co;
            #pragma unroll
            for (int u = 0; u < 4; ++u) {
                const int r = u * 32 + (tid >> 3);
                float4 v = aCur[u];
                ushort4 hh, ll;
                hh.x = bf_hi(v.x); ll.x = bf_lo(v.x, hh.x);
                hh.y = bf_hi(v.y); ll.y = bf_lo(v.y, hh.y);
                hh.z = bf_hi(v.z); ll.z = bf_lo(v.z, hh.z);
                hh.w = bf_hi(v.w); ll.w = bf_lo(v.w, hh.w);
                *(ushort4*)(dh + r * LDS_STRIDE) = hh;
                *(ushort4*)(dl + r * LDS_STRIDE) = ll;
            }
        }
        if (kc + 1 < NKC) { CP_WAIT(1); } else { CP_WAIT(0); }
        __syncthreads();                          // planes + B(st) visible

        if (kc + 1 < NKC) ldgA(aNext, A, m0, kc + 1, tid);   // hide under mma

        const uint32_t aHi = sb + APL_OFF(st, 0) + a_off * 2;
        const uint32_t aLo = sb + APL_OFF(st, 1) + a_off * 2;
        const uint32_t bHi = sb + B_OFF(st, 0) + b_off * 2;
        const uint32_t bLo = sb + B_OFF(st, 1) + b_off * 2;

        #pragma unroll
        for (int ks = 0; ks < 2; ++ks) {
            const uint32_t kbb = ks * 32;          // 16 ushorts = 32 bytes
            uint32_t ah[2][4], al[2][4];
            #pragma unroll
            for (int i = 0; i < 2; ++i) {
                ldsm4(ah[i], aHi + i * (16 * LDS_STRIDE * 2) + kbb);
                ldsm4(al[i], aLo + i * (16 * LDS_STRIDE * 2) + kbb);
            }
            #pragma unroll
            for (int jp = 0; jp < 4; ++jp) {
                uint32_t bh[4], bl[4];
                ldsm4(bh, bHi + jp * (16 * LDS_STRIDE * 2) + kbb);
                ldsm4(bl, bLo + jp * (16 * LDS_STRIDE * 2) + kbb);
                #pragma unroll
                for (int jj = 0; jj < 2; ++jj) {
                    #pragma unroll
                    for (int i = 0; i < 2; ++i) {
                        mma_bf16(c[i][2 * jp + jj], ah[i], bh + 2 * jj);
                        mma_bf16(c[i][2 * jp + jj], al[i], bh + 2 * jj);
                        mma_bf16(c[i][2 * jp + jj], ah[i], bl + 2 * jj);
                    }
                }
            }
        }
        #pragma unroll
        for (int u = 0; u < 4; ++u) aCur[u] = aNext[u];
    }

    #pragma unroll
    for (int j = 0; j < 8; ++j) {
        const int col = n0 + wn + j * 8 + 2 * t;
        const float2 bv = *(const float2*)&bias[col];
        #pragma unroll
        for (int i = 0; i < 2; ++i) {
            const int row = m0 + wm + i * 16 + g;
            float2 v0 = { c[i][j][0] + bv.x, c[i][j][1] + bv.y };
            float2 v1 = { c[i][j][2] + bv.x, c[i][j][3] + bv.y };
            *(float2*)&g_logits[(size_t)row * NDIM + col]       = v0;
            *(float2*)&g_logits[(size_t)(row + 8) * NDIM + col] = v1;
        }
    }
}

// ---------------------------------------------------------------------------
// fused_k: gumbel-softmax -> bf16 hi/lo prob planes in smem, in-register
// soft-marginal, then P2 einsum on tensor cores fed by the coalesced
// cb fragment table.  (unchanged from R15)
// ---------------------------------------------------------------------------
__global__ void fused_k(const float* __restrict__ gumbels,
                        const int* __restrict__ mask,
                        float* __restrict__ out) {
    extern __shared__ unsigned short probs_bf[];   // [g][plane][32][PSTRIDE]
    __shared__ float wpart[8][VPG];
    __shared__ float sm_mask[RPB];

    const int tid  = threadIdx.x;
    const int lane = tid & 31;
    const int warp = tid >> 5;
    const int r0   = blockIdx.x * RPB;

    if (tid < RPB) sm_mask[tid] = mask[r0 + tid] ? 1.0f : 0.0f;
    __syncthreads();

    const int g1    = warp & 1;
    const int rbase = warp >> 1;
    const int goff  = g1 * VPG;
    unsigned short* ph = probs_bf + (g1 * 2 + 0) * TILE_P;
    unsigned short* pl = probs_bf + (g1 * 2 + 1) * TILE_P;

    float macc[10];
    #pragma unroll
    for (int j = 0; j < 10; j++) macc[j] = 0.f;

    #pragma unroll 1
    for (int k = 0; k < 8; ++k) {
        const int r = rbase + 4 * k;
        const float* lrow = &g_logits[(size_t)(r0 + r) * NDIM + goff];
        const float* grow = &gumbels [(size_t)(r0 + r) * NDIM + goff];
        float l[10], x1[10];
        float m1 = -1e30f, m2 = -1e30f;
        #pragma unroll
        for (int j = 0; j < 10; j++) {
            const int v = lane + j * 32;
            l[j]  = lrow[v];
            x1[j] = (l[j] + grow[v]) * 0.5f;
            m1 = fmaxf(m1, x1[j]); m2 = fmaxf(m2, l[j]);
        }
        #pragma unroll
        for (int o = 16; o; o >>= 1) {
            m1 = fmaxf(m1, __shfl_xor_sync(0xffffffffu, m1, o));
            m2 = fmaxf(m2, __shfl_xor_sync(0xffffffffu, m2, o));
        }
        float e1[10], e2[10], s1 = 0.f, s2 = 0.f;
        #pragma unroll
        for (int j = 0; j < 10; j++) {
            e1[j] = __expf(x1[j] - m1); s1 += e1[j];
            e2[j] = __expf(l[j]  - m2); s2 += e2[j];
        }
        #pragma unroll
        for (int o = 16; o; o >>= 1) {
            s1 += __shfl_xor_sync(0xffffffffu, s1, o);
            s2 += __shfl_xor_sync(0xffffffffu, s2, o);
        }
        const float inv1 = 1.0f / s1;
        const float inv2 = 1.0f / s2;
        const float mk = sm_mask[r];
        #pragma unroll
        for (int j = 0; j < 10; j++) {
            const int v = lane + j * 32;
            const float p = e1[j] * inv1;
            const unsigned short h = bf_hi(p);
            ph[r * PSTRIDE + v] = h;
            pl[r * PSTRIDE + v] = bf_lo(p, h);
            macc[j] = fmaf(mk, e2[j] * inv2, macc[j]);
        }
    }
    #pragma unroll
    for (int j = 0; j < 10; j++) wpart[warp][lane + j * 32] = macc[j];
    __syncthreads();

    for (int c = tid; c < GV; c += 256) {
        const int gg = (c >= VPG);
        const int cc = c - gg * VPG;
        g_partial[(size_t)blockIdx.x * GV + c] =
            wpart[gg][cc] + wpart[gg + 2][cc] + wpart[gg + 4][cc] + wpart[gg + 6][cc];
    }

    const int g  = warp >> 2;
    const int nq = warp & 3;
    const uint32_t sbp = smem_u32(probs_bf);
    const uint32_t aHi = sbp + ((g * 2) * TILE_P
                         + (lane & 15) * PSTRIDE + ((lane >> 4) << 3)) * 2;
    const uint32_t aLo = aHi + TILE_P * 2;
    const uint4* __restrict__ Fw = g_cbf + ((g * 16 + nq * 4) * 20) * 32 + lane;

    float c[2][4][4];
    #pragma unroll
    for (int i = 0; i < 2; i++)
        #pragma unroll
        for (int j = 0; j < 4; j++)
            #pragma unroll
            for (int q = 0; q < 4; q++) c[i][j][q] = 0.f;

    #pragma unroll 4
    for (int kk = 0; kk < VPG / 16; ++kk) {
        uint32_t ah[2][4], al[2][4];
        #pragma unroll
        for (int i = 0; i < 2; ++i) {
            ldsm4(ah[i], aHi + (i * 16 * PSTRIDE + kk * 16) * 2);
            ldsm4(al[i], aLo + (i * 16 * PSTRIDE + kk * 16) * 2);
        }
        #pragma unroll
        for (int jj = 0; jj < 4; ++jj) {
            const uint4 f = Fw[(jj * 20 + kk) * 32];     // coalesced LDG.128
            uint32_t bh[2] = { f.x, f.y };
            uint32_t bl[2] = { f.z, f.w };
            #pragma unroll
            for (int i = 0; i < 2; ++i) {
                mma_bf16(c[i][jj], ah[i], bh);
                mma_bf16(c[i][jj], al[i], bh);
                mma_bf16(c[i][jj], ah[i], bl);
            }
        }
    }

    #pragma unroll
    for (int jj = 0; jj < 4; ++jj) {
        const int d = nq * 32 + jj * 8 + (lane & 3) * 2;
        #pragma unroll
        for (int i = 0; i < 2; ++i) {
            const int row = r0 + i * 16 + (lane >> 2);
            *(float2*)&out[(size_t)row * 256 + g * 128 + d] =
                make_float2(c[i][jj][0], c[i][jj][1]);
            *(float2*)&out[(size_t)(row + 8) * 256 + g * 128 + d] =
                make_float2(c[i][jj][2], c[i][jj][3]);
        }
    }
}

// ---------------------------------------------------------------------------
__global__ void reduce_marginal_k() {
    const int lane = threadIdx.x & 31;
    const int warp = threadIdx.x >> 5;
    const int c = blockIdx.x * 32 + lane;
    float s = 0.f;
    for (int b = warp; b < NBLK; b += 8)
        s += g_partial[(size_t)b * GV + c];
    __shared__ float red[8][32];
    red[warp][lane] = s;
    __syncthreads();
    if (warp == 0) {
        float v = red[0][lane];
        #pragma unroll
        for (int i = 1; i < 8; i++) v += red[i][lane];
        g_marginal[c] = v;
    }
}

// ---------------------------------------------------------------------------
__global__ void finalize_k(const int* __restrict__ mask,
                           float* __restrict__ out, int out_size) {
    __shared__ double red0[1024], red1[1024];
    __shared__ int    redi[1024];
    const int tid = threadIdx.x;
    const int4* m4 = (const int4*)mask;
    int cnt = 0;
    for (int i = tid; i < M_ROWS / 4; i += 1024) {
        int4 v = m4[i];
        cnt += (v.x != 0) + (v.y != 0) + (v.z != 0) + (v.w != 0);
    }
    redi[tid] = cnt; __syncthreads();
    for (int o = 512; o; o >>= 1) { if (tid < o) redi[tid] += redi[tid + o]; __syncthreads(); }
    const double inv = 1.0 / (double)redi[0];

    double s0 = 0.0, s1 = 0.0;
    for (int c = tid; c < GV; c += 1024) {
        const double m = (double)g_marginal[c] * inv;
        const double tt = m * log(m + 1e-7);
        if (c < VPG) s0 += tt; else s1 += tt;
    }
    red0[tid] = s0; red1[tid] = s1; __syncthreads();
    for (int o = 512; o; o >>= 1) {
        if (tid < o) { red0[tid] += red0[tid + o]; red1[tid] += red1[tid + o]; }
        __syncthreads();
    }
    if (tid == 0) out[out_size - 1] = (float)(exp(-red0[0]) + exp(-red1[0]));
}

// ---------------------------------------------------------------------------
extern "C" void kernel_launch(void* const* d_in, const int* in_sizes, int n_in,
                              void* d_out, int out_size) {
    const float* hs   = (const float*)d_in[0];
    const float* gum  = (const float*)d_in[1];
    const float* W    = (const float*)d_in[2];
    const float* bias = (const float*)d_in[3];
    const float* cb   = (const float*)d_in[4];
    const int*   mask = (const int*)d_in[5];
    float* out = (float*)d_out;

    static int attr_done = 0;
    if (!attr_done) {
        cudaFuncSetAttribute(mma_gemm, cudaFuncAttributeMaxDynamicSharedMemorySize, SMEM_GEMM);
        cudaFuncSetAttribute(fused_k,  cudaFuncAttributeMaxDynamicSharedMemorySize, SMEM_FUSED);
        attr_done = 1;
    }

    conv_w<<<(NDIM * KDIM + 255) / 256, 256>>>(W);
    conv_cb<<<(2 * 16 * 20 * 32 + 255) / 256, 256>>>(cb);
    mma_gemm<<<dim3(NDIM / NT, M_ROWS / MT), 256, SMEM_GEMM>>>(hs, bias);
    fused_k<<<NBLK, 256, SMEM_FUSED>>>(gum, mask, out);
    reduce_marginal_k<<<GV / 32, 256>>>();
    finalize_k<<<1, 1024>>>(mask, out, out_size);
}

// round 17
// speedup vs baseline: 1.8696x; 1.0207x over previous
#include <cuda_runtime.h>
#include <cuda_bf16.h>
#include <cstdint>

#define M_ROWS 65536     // B*T
#define KDIM   512       // H
#define NDIM   640       // G*V
#define GV     640
#define VPG    320
#define DPG    128
#define RPB    32
#define NBLK   (M_ROWS / RPB)

// GEMM tiling
#define MT 128
#define NT 128
#define KC 32
#define NKC (KDIM / KC)          // 16
#define LDS_STRIDE 40            // ushorts, bf16 tiles (pad 8)

// gemm smem byte offsets (dynamic): B planes 2-stage + A planes 2-stage
#define BPL_BYTES 10240                               // one plane tile 128x40 bf16
#define B_OFF(st, pl)  (((st) * 2 + (pl)) * BPL_BYTES)          // 0..40960
#define APL_OFF(st, pl) (40960 + ((st) * 2 + (pl)) * BPL_BYTES) // 40960..81920
#define SMEM_GEMM 81920

// fused_k: bf16 hi/lo prob planes for ldmatrix (stride 328 -> conflict-free)
#define PSTRIDE 328
#define TILE_P  (32 * PSTRIDE)              // ushorts per (group, plane)
#define SMEM_FUSED (4 * TILE_P * 2)         // 83968 bytes

// Scratch (device globals: allocation-free per harness rules)
__device__ float g_logits[(size_t)M_ROWS * NDIM];            // 160 MB
__device__ float g_partial[(size_t)NBLK * GV];               // 5.2 MB
__device__ float g_marginal[GV];
__device__ unsigned short g_wt_hi[(size_t)NDIM * KDIM];      // W^T hi [640][512]
__device__ unsigned short g_wt_lo[(size_t)NDIM * KDIM];
__device__ uint4 g_cbf[2 * 16 * 20 * 32];                    // cb frag table, 320 KB

// ---------------------------------------------------------------------------
__device__ __forceinline__ void mma_bf16(float* c, const uint32_t* a, const uint32_t* b) {
    asm volatile(
        "mma.sync.aligned.m16n8k16.row.col.f32.bf16.bf16.f32 "
        "{%0,%1,%2,%3}, {%4,%5,%6,%7}, {%8,%9}, {%0,%1,%2,%3};"
        : "+f"(c[0]), "+f"(c[1]), "+f"(c[2]), "+f"(c[3])
        : "r"(a[0]), "r"(a[1]), "r"(a[2]), "r"(a[3]), "r"(b[0]), "r"(b[1]));
}
__device__ __forceinline__ void ldsm4(uint32_t* r, uint32_t addr) {
    asm volatile("ldmatrix.sync.aligned.m8n8.x4.shared.b16 {%0,%1,%2,%3}, [%4];"
        : "=r"(r[0]), "=r"(r[1]), "=r"(r[2]), "=r"(r[3]) : "r"(addr));
}
__device__ __forceinline__ unsigned short bf_hi(float x) {
    return __bfloat16_as_ushort(__float2bfloat16_rn(x));
}
__device__ __forceinline__ unsigned short bf_lo(float x, unsigned short h) {
    return __bfloat16_as_ushort(
        __float2bfloat16_rn(x - __bfloat162float(__ushort_as_bfloat16(h))));
}
__device__ __forceinline__ uint32_t smem_u32(const void* p) {
    uint32_t a;
    asm("{ .reg .u64 t; cvta.to.shared.u64 t, %1; cvt.u32.u64 %0, t; }" : "=r"(a) : "l"(p));
    return a;
}
__device__ __forceinline__ void cp_async16(uint32_t dst, const void* src) {
    asm volatile("cp.async.cg.shared.global [%0], [%1], 16;" :: "r"(dst), "l"(src));
}
#define CP_COMMIT() asm volatile("cp.async.commit_group;" ::: "memory")
#define CP_WAIT(n)  asm volatile("cp.async.wait_group %0;" :: "n"(n) : "memory")

// ---------------------------------------------------------------------------
// conv_all: W^T hi/lo planes + cb fragment table in one launch
// ---------------------------------------------------------------------------
__global__ void conv_all(const float* __restrict__ W, const float* __restrict__ cb) {
    int idx = blockIdx.x * 256 + threadIdx.x;
    if (idx < NDIM * KDIM) {
        int n = idx >> 9, k = idx & 511;
        float x = W[(size_t)k * NDIM + n];
        unsigned short h = bf_hi(x);
        g_wt_hi[idx] = h;
        g_wt_lo[idx] = bf_lo(x, h);
    }
    int idx2 = idx - NDIM * KDIM;
    if (idx2 >= 0 && idx2 < 2 * 16 * 20 * 32) {
        int lane = idx2 & 31;
        int kk = (idx2 >> 5) % 20;
        int db = (idx2 >> 5) / 20 % 16;
        int g  = idx2 / (32 * 20 * 16);
        int d = db * 8 + (lane >> 2);
        int v = kk * 16 + (lane & 3) * 2;
        float x00 = cb[(size_t)(g * VPG + v)     * DPG + d];
        float x01 = cb[(size_t)(g * VPG + v + 1) * DPG + d];
        float x10 = cb[(size_t)(g * VPG + v + 8) * DPG + d];
        float x11 = cb[(size_t)(g * VPG + v + 9) * DPG + d];
        unsigned short h00 = bf_hi(x00), h01 = bf_hi(x01);
        unsigned short h10 = bf_hi(x10), h11 = bf_hi(x11);
        uint4 f;
        f.x = (uint32_t)h00 | ((uint32_t)h01 << 16);
        f.y = (uint32_t)h10 | ((uint32_t)h11 << 16);
        f.z = (uint32_t)bf_lo(x00, h00) | ((uint32_t)bf_lo(x01, h01) << 16);
        f.w = (uint32_t)bf_lo(x10, h10) | ((uint32_t)bf_lo(x11, h11) << 16);
        g_cbf[idx2] = f;
    }
}

// ---------------------------------------------------------------------------
// mma_gemm: cp.async B (double-buffered) + register-converted A planes
// (double-buffered), 2 syncs/iter, bf16-split 3-pass mma.sync. (unchanged)
// ---------------------------------------------------------------------------
__device__ __forceinline__ void issueB(uint32_t sb, int stage, int n0, int kc, int tid) {
    #pragma unroll
    for (int u = 0; u < 2; ++u) {
        const int idx = u * 256 + tid;                 // 0..511
        const int r = idx >> 2, cc = idx & 3;
        const size_t gb = (size_t)(n0 + r) * KDIM + kc * KC + cc * 8;
        const uint32_t so = (uint32_t)(r * LDS_STRIDE + cc * 8) * 2;
        cp_async16(sb + B_OFF(stage, 0) + so, g_wt_hi + gb);
        cp_async16(sb + B_OFF(stage, 1) + so, g_wt_lo + gb);
    }
}

__device__ __forceinline__ void ldgA(float4* a, const float* __restrict__ A,
                                     int m0, int kc, int tid) {
    const int c = (tid & 7) * 4;
    #pragma unroll
    for (int u = 0; u < 4; ++u) {
        const int r = u * 32 + (tid >> 3);
        a[u] = *(const float4*)&A[(size_t)(m0 + r) * KDIM + kc * KC + c];
    }
}

__global__ void __launch_bounds__(256, 2)
mma_gemm(const float* __restrict__ A, const float* __restrict__ bias) {
    extern __shared__ char smg[];
    const uint32_t sb = smem_u32(smg);

    const int tid  = threadIdx.x;
    const int wid  = tid >> 5;
    const int lane = tid & 31;
    const int g    = lane >> 2;
    const int t    = lane & 3;
    const int n0   = blockIdx.x * NT;
    const int m0   = blockIdx.y * MT;
    const int wm   = (wid & 3) * 32;
    const int wn   = (wid >> 2) * 64;

    const uint32_t a_off = (uint32_t)((wm + (lane & 15)) * LDS_STRIDE + ((lane >> 4) << 3));
    const uint32_t b_off = (uint32_t)((wn + ((lane >> 4) << 3) + (lane & 7)) * LDS_STRIDE
                                      + (((lane >> 3) & 1) << 3));

    float c[2][8][4];
    #pragma unroll
    for (int i = 0; i < 2; i++)
        #pragma unroll
        for (int j = 0; j < 8; j++)
            #pragma unroll
            for (int q = 0; q < 4; q++) c[i][j][q] = 0.f;

    float4 aCur[4], aNext[4];
    ldgA(aCur, A, m0, 0, tid);
    issueB(sb, 0, n0, 0, tid);
    CP_COMMIT();

    #pragma unroll 2
    for (int kc = 0; kc < NKC; ++kc) {
        const int st = kc & 1;
        __syncthreads();                          // mma(kc-1) fully done
        if (kc + 1 < NKC) { issueB(sb, st ^ 1, n0, kc + 1, tid); CP_COMMIT(); }

        {
            const int co = (tid & 7) * 4;
            unsigned short* dh = (unsigned short*)(smg + APL_OFF(st, 0)) + co;
            unsigned short* dl = (unsigned short*)(smg + APL_OFF(st, 1)) + co;
            #pragma unroll
            for (int u = 0; u < 4; ++u) {
                const int r = u * 32 + (tid >> 3);
                float4 v = aCur[u];
                ushort4 hh, ll;
                hh.x = bf_hi(v.x); ll.x = bf_lo(v.x, hh.x);
                hh.y = bf_hi(v.y); ll.y = bf_lo(v.y, hh.y);
                hh.z = bf_hi(v.z); ll.z = bf_lo(v.z, hh.z);
                hh.w = bf_hi(v.w); ll.w = bf_lo(v.w, hh.w);
                *(ushort4*)(dh + r * LDS_STRIDE) = hh;
                *(ushort4*)(dl + r * LDS_STRIDE) = ll;
            }
        }
        if (kc + 1 < NKC) { CP_WAIT(1); } else { CP_WAIT(0); }
        __syncthreads();                          // planes + B(st) visible

        if (kc + 1 < NKC) ldgA(aNext, A, m0, kc + 1, tid);   // hide under mma

        const uint32_t aHi = sb + APL_OFF(st, 0) + a_off * 2;
        const uint32_t aLo = sb + APL_OFF(st, 1) + a_off * 2;
        const uint32_t bHi = sb + B_OFF(st, 0) + b_off * 2;
        const uint32_t bLo = sb + B_OFF(st, 1) + b_off * 2;

        #pragma unroll
        for (int ks = 0; ks < 2; ++ks) {
            const uint32_t kbb = ks * 32;          // 16 ushorts = 32 bytes
            uint32_t ah[2][4], al[2][4];
            #pragma unroll
            for (int i = 0; i < 2; ++i) {
                ldsm4(ah[i], aHi + i * (16 * LDS_STRIDE * 2) + kbb);
                ldsm4(al[i], aLo + i * (16 * LDS_STRIDE * 2) + kbb);
            }
            #pragma unroll
            for (int jp = 0; jp < 4; ++jp) {
                uint32_t bh[4], bl[4];
                ldsm4(bh, bHi + jp * (16 * LDS_STRIDE * 2) + kbb);
                ldsm4(bl, bLo + jp * (16 * LDS_STRIDE * 2) + kbb);
                #pragma unroll
                for (int jj = 0; jj < 2; ++jj) {
                    #pragma unroll
                    for (int i = 0; i < 2; ++i) {
                        mma_bf16(c[i][2 * jp + jj], ah[i], bh + 2 * jj);
                        mma_bf16(c[i][2 * jp + jj], al[i], bh + 2 * jj);
                        mma_bf16(c[i][2 * jp + jj], ah[i], bl + 2 * jj);
                    }
                }
            }
        }
        #pragma unroll
        for (int u = 0; u < 4; ++u) aCur[u] = aNext[u];
    }

    #pragma unroll
    for (int j = 0; j < 8; ++j) {
        const int col = n0 + wn + j * 8 + 2 * t;
        const float2 bv = *(const float2*)&bias[col];
        #pragma unroll
        for (int i = 0; i < 2; ++i) {
            const int row = m0 + wm + i * 16 + g;
            float2 v0 = { c[i][j][0] + bv.x, c[i][j][1] + bv.y };
            float2 v1 = { c[i][j][2] + bv.x, c[i][j][3] + bv.y };
            *(float2*)&g_logits[(size_t)row * NDIM + col]       = v0;
            *(float2*)&g_logits[(size_t)(row + 8) * NDIM + col] = v1;
        }
    }
}

// ---------------------------------------------------------------------------
// fused_k: P1 gumbel-softmax with SOFTWARE-PIPELINED row loads, in-register
// soft-marginal; P2 einsum on tensor cores (unchanged).
// ---------------------------------------------------------------------------
__global__ void fused_k(const float* __restrict__ gumbels,
                        const int* __restrict__ mask,
                        float* __restrict__ out) {
    extern __shared__ unsigned short probs_bf[];   // [g][plane][32][PSTRIDE]
    __shared__ float wpart[8][VPG];
    __shared__ float sm_mask[RPB];

    const int tid  = threadIdx.x;
    const int lane = tid & 31;
    const int warp = tid >> 5;
    const int r0   = blockIdx.x * RPB;

    if (tid < RPB) sm_mask[tid] = mask[r0 + tid] ? 1.0f : 0.0f;
    __syncthreads();

    const int g1    = warp & 1;
    const int rbase = warp >> 1;
    const int goff  = g1 * VPG;
    unsigned short* ph = probs_bf + (g1 * 2 + 0) * TILE_P;
    unsigned short* pl = probs_bf + (g1 * 2 + 1) * TILE_P;

    float macc[10];
    #pragma unroll
    for (int j = 0; j < 10; j++) macc[j] = 0.f;

    float l[10], gm[10];
    {   // prefetch k = 0
        const float* lrow = &g_logits[(size_t)(r0 + rbase) * NDIM + goff];
        const float* grow = &gumbels [(size_t)(r0 + rbase) * NDIM + goff];
        #pragma unroll
        for (int j = 0; j < 10; j++) {
            const int v = lane + j * 32;
            l[j]  = lrow[v];
            gm[j] = grow[v];
        }
    }

    #pragma unroll 1
    for (int k = 0; k < 8; ++k) {
        const int r = rbase + 4 * k;
        float ln[10], gn[10];
        if (k < 7) {    // issue next row's loads before this row's compute
            const float* lrow = &g_logits[(size_t)(r0 + r + 4) * NDIM + goff];
            const float* grow = &gumbels [(size_t)(r0 + r + 4) * NDIM + goff];
            #pragma unroll
            for (int j = 0; j < 10; j++) {
                const int v = lane + j * 32;
                ln[j] = lrow[v];
                gn[j] = grow[v];
            }
        }

        float x1[10];
        float m1 = -1e30f, m2 = -1e30f;
        #pragma unroll
        for (int j = 0; j < 10; j++) {
            x1[j] = (l[j] + gm[j]) * 0.5f;
            m1 = fmaxf(m1, x1[j]); m2 = fmaxf(m2, l[j]);
        }
        #pragma unroll
        for (int o = 16; o; o >>= 1) {
            m1 = fmaxf(m1, __shfl_xor_sync(0xffffffffu, m1, o));
            m2 = fmaxf(m2, __shfl_xor_sync(0xffffffffu, m2, o));
        }
        float e1[10], e2[10], s1 = 0.f, s2 = 0.f;
        #pragma unroll
        for (int j = 0; j < 10; j++) {
            e1[j] = __expf(x1[j] - m1); s1 += e1[j];
            e2[j] = __expf(l[j]  - m2); s2 += e2[j];
        }
        #pragma unroll
        for (int o = 16; o; o >>= 1) {
            s1 += __shfl_xor_sync(0xffffffffu, s1, o);
            s2 += __shfl_xor_sync(0xffffffffu, s2, o);
        }
        const float inv1 = 1.0f / s1;
        const float inv2 = 1.0f / s2;
        const float mk = sm_mask[r];
        #pragma unroll
        for (int j = 0; j < 10; j++) {
            const int v = lane + j * 32;
            const float p = e1[j] * inv1;
            const unsigned short h = bf_hi(p);
            ph[r * PSTRIDE + v] = h;
            pl[r * PSTRIDE + v] = bf_lo(p, h);
            macc[j] = fmaf(mk, e2[j] * inv2, macc[j]);
        }
        #pragma unroll
        for (int j = 0; j < 10; j++) { l[j] = ln[j]; gm[j] = gn[j]; }
    }
    #pragma unroll
    for (int j = 0; j < 10; j++) wpart[warp][lane + j * 32] = macc[j];
    __syncthreads();

    for (int c = tid; c < GV; c += 256) {
        const int gg = (c >= VPG);
        const int cc = c - gg * VPG;
        g_partial[(size_t)blockIdx.x * GV + c] =
            wpart[gg][cc] + wpart[gg + 2][cc] + wpart[gg + 4][cc] + wpart[gg + 6][cc];
    }

    const int g  = warp >> 2;
    const int nq = warp & 3;
    const uint32_t sbp = smem_u32(probs_bf);
    const uint32_t aHi = sbp + ((g * 2) * TILE_P
                         + (lane & 15) * PSTRIDE + ((lane >> 4) << 3)) * 2;
    const uint32_t aLo = aHi + TILE_P * 2;
    const uint4* __restrict__ Fw = g_cbf + ((g * 16 + nq * 4) * 20) * 32 + lane;

    float c[2][4][4];
    #pragma unroll
    for (int i = 0; i < 2; i++)
        #pragma unroll
        for (int j = 0; j < 4; j++)
            #pragma unroll
            for (int q = 0; q < 4; q++) c[i][j][q] = 0.f;

    #pragma unroll 4
    for (int kk = 0; kk < VPG / 16; ++kk) {
        uint32_t ah[2][4], al[2][4];
        #pragma unroll
        for (int i = 0; i < 2; ++i) {
            ldsm4(ah[i], aHi + (i * 16 * PSTRIDE + kk * 16) * 2);
            ldsm4(al[i], aLo + (i * 16 * PSTRIDE + kk * 16) * 2);
        }
        #pragma unroll
        for (int jj = 0; jj < 4; ++jj) {
            const uint4 f = Fw[(jj * 20 + kk) * 32];     // coalesced LDG.128
            uint32_t bh[2] = { f.x, f.y };
            uint32_t bl[2] = { f.z, f.w };
            #pragma unroll
            for (int i = 0; i < 2; ++i) {
                mma_bf16(c[i][jj], ah[i], bh);
                mma_bf16(c[i][jj], al[i], bh);
                mma_bf16(c[i][jj], ah[i], bl);
            }
        }
    }

    #pragma unroll
    for (int jj = 0; jj < 4; ++jj) {
        const int d = nq * 32 + jj * 8 + (lane & 3) * 2;
        #pragma unroll
        for (int i = 0; i < 2; ++i) {
            const int row = r0 + i * 16 + (lane >> 2);
            *(float2*)&out[(size_t)row * 256 + g * 128 + d] =
                make_float2(c[i][jj][0], c[i][jj][1]);
            *(float2*)&out[(size_t)(row + 8) * 256 + g * 128 + d] =
                make_float2(c[i][jj][2], c[i][jj][3]);
        }
    }
}

// ---------------------------------------------------------------------------
__global__ void reduce_marginal_k() {
    const int lane = threadIdx.x & 31;
    const int warp = threadIdx.x >> 5;
    const int c = blockIdx.x * 32 + lane;
    float s = 0.f;
    for (int b = warp; b < NBLK; b += 8)
        s += g_partial[(size_t)b * GV + c];
    __shared__ float red[8][32];
    red[warp][lane] = s;
    __syncthreads();
    if (warp == 0) {
        float v = red[0][lane];
        #pragma unroll
        for (int i = 1; i < 8; i++) v += red[i][lane];
        g_marginal[c] = v;
    }
}

// ---------------------------------------------------------------------------
__global__ void finalize_k(const int* __restrict__ mask,
                           float* __restrict__ out, int out_size) {
    __shared__ double red0[1024], red1[1024];
    __shared__ int    redi[1024];
    const int tid = threadIdx.x;
    const int4* m4 = (const int4*)mask;
    int cnt = 0;
    for (int i = tid; i < M_ROWS / 4; i += 1024) {
        int4 v = m4[i];
        cnt += (v.x != 0) + (v.y != 0) + (v.z != 0) + (v.w != 0);
    }
    redi[tid] = cnt; __syncthreads();
    for (int o = 512; o; o >>= 1) { if (tid < o) redi[tid] += redi[tid + o]; __syncthreads(); }
    const double inv = 1.0 / (double)redi[0];

    double s0 = 0.0, s1 = 0.0;
    for (int c = tid; c < GV; c += 1024) {
        const double m = (double)g_marginal[c] * inv;
        const double tt = m * log(m + 1e-7);
        if (c < VPG) s0 += tt; else s1 += tt;
    }
    red0[tid] = s0; red1[tid] = s1; __syncthreads();
    for (int o = 512; o; o >>= 1) {
        if (tid < o) { red0[tid] += red0[tid + o]; red1[tid] += red1[tid + o]; }
        __syncthreads();
    }
    if (tid == 0) out[out_size - 1] = (float)(exp(-red0[0]) + exp(-red1[0]));
}

// ---------------------------------------------------------------------------
extern "C" void kernel_launch(void* const* d_in, const int* in_sizes, int n_in,
                              void* d_out, int out_size) {
    const float* hs   = (const float*)d_in[0];
    const float* gum  = (const float*)d_in[1];
    const float* W    = (const float*)d_in[2];
    const float* bias = (const float*)d_in[3];
    const float* cb   = (const float*)d_in[4];
    const int*   mask = (const int*)d_in[5];
    float* out = (float*)d_out;

    static int attr_done = 0;
    if (!attr_done) {
        cudaFuncSetAttribute(mma_gemm, cudaFuncAttributeMaxDynamicSharedMemorySize, SMEM_GEMM);
        cudaFuncSetAttribute(fused_k,  cudaFuncAttributeMaxDynamicSharedMemorySize, SMEM_FUSED);
        attr_done = 1;
    }

    conv_all<<<(NDIM * KDIM + 2 * 16 * 20 * 32 + 255) / 256, 256>>>(W, cb);
    mma_gemm<<<dim3(NDIM / NT, M_ROWS / MT), 256, SMEM_GEMM>>>(hs, bias);
    fused_k<<<NBLK, 256, SMEM_FUSED>>>(gum, mask, out);
    reduce_marginal_k<<<GV / 32, 256>>>();
    finalize_k<<<1, 1024>>>(mask, out, out_size);
}